// round 12
// baseline (speedup 1.0000x reference)
#include <cuda_runtime.h>
#include <cstdint>

#define IMG_D 224
#define HW (IMG_D * IMG_D)
#define NBATCH 64

#define R_TILE 8
#define HALO 3
#define WMAX (R_TILE + 2 * HALO)        // 14 rows staged
#define TILES_PER_IMG (IMG_D / R_TILE)  // 28
#define TPB 448                         // 2 sub-rows x 224 cols
#define ROWSUB 2
#define PXT (R_TILE / ROWSUB)           // 4 pixels per thread
#define PLANE_W (WMAX * IMG_D)          // 3136 floats
#define PLANE_BYTES (PLANE_W * 4)       // 12544 B
#define SMEM_BYTES (6 * PLANE_BYTES)    // 75264 B -> 3 blocks/SM

// R11 (split-image TMA staging: im1 planes -> mbar0, im2 -> mbar1;
// img-outer compute hides im2's fill behind im1's gathers) with HALO=3
// so three blocks fit per SM (3 x 75.3KB smem, regs capped at 48):
// with 3 co-resident blocks, at least one is in compute phase at any
// time, covering the remaining fill-latency exposure. The narrower
// window raises the global-fallback rate to ~0.27%/coord (~8% of
// warp-img iterations touch the slow path) — the measured R7 cost of
// this (~1us) should now be outweighed by the fill hiding.
__global__ __launch_bounds__(TPB, 3)
void view_morph12_kernel(
    const float* __restrict__ im1,
    const float* __restrict__ im2,
    const float* __restrict__ C,
    const float* __restrict__ M1,
    const float* __restrict__ M2,
    float* __restrict__ out)
{
    extern __shared__ float sp[];
    __shared__ alignas(8) uint64_t mbar_storage[2];

    int blk = blockIdx.x;
    int n = blk / TILES_PER_IMG;
    int tile = blk - n * TILES_PER_IMG;
    int r0 = tile * R_TILE;

    int wl = max(0, r0 - HALO);
    int wh = min(IMG_D - 1, r0 + R_TILE - 1 + HALO);
    int wc = wh - wl + 1;

    int tid = threadIdx.x;
    int col = tid % IMG_D;
    int rsub = tid / IMG_D;

    const float* b1 = im1 + (size_t)n * 3 * HW;
    const float* b2 = im2 + (size_t)n * 3 * HW;

    uint32_t mbar0 = (uint32_t)__cvta_generic_to_shared(&mbar_storage[0]);
    uint32_t mbar1 = (uint32_t)__cvta_generic_to_shared(&mbar_storage[1]);
    uint32_t spb0  = (uint32_t)__cvta_generic_to_shared(sp);

    if (tid == 0) {
        asm volatile("mbarrier.init.shared.b64 [%0], 1;" :: "r"(mbar0) : "memory");
        asm volatile("mbarrier.init.shared.b64 [%0], 1;" :: "r"(mbar1) : "memory");
    }
    __syncthreads();

    if (tid == 0) {
        uint32_t copy_bytes = (uint32_t)(wc * IMG_D * 4);
        asm volatile("mbarrier.arrive.expect_tx.shared.b64 _, [%0], %1;"
                     :: "r"(mbar0), "r"(copy_bytes * 3) : "memory");
        asm volatile("mbarrier.arrive.expect_tx.shared.b64 _, [%0], %1;"
                     :: "r"(mbar1), "r"(copy_bytes * 3) : "memory");
        #pragma unroll
        for (int pl = 0; pl < 3; pl++) {     // im1 planes -> mbar0
            const float* src = b1 + pl * HW + wl * IMG_D;
            asm volatile(
                "cp.async.bulk.shared::cta.global.mbarrier::complete_tx::bytes"
                " [%0], [%1], %2, [%3];"
                :: "r"(spb0 + pl * PLANE_BYTES), "l"(src),
                   "r"(copy_bytes), "r"(mbar0) : "memory");
        }
        #pragma unroll
        for (int pl = 0; pl < 3; pl++) {     // im2 planes -> mbar1
            const float* src = b2 + pl * HW + wl * IMG_D;
            asm volatile(
                "cp.async.bulk.shared::cta.global.mbarrier::complete_tx::bytes"
                " [%0], [%1], %2, [%3];"
                :: "r"(spb0 + (pl + 3) * PLANE_BYTES), "l"(src),
                   "r"(copy_bytes), "r"(mbar1) : "memory");
        }
    }

    // ── prefetch C/M while TMA runs ──
    const float* Cn  = C  + (size_t)n * 2 * HW;
    const float* M1n = M1 + (size_t)n * HW;
    const float* M2n = M2 + (size_t)n * HW;

    float cx[PXT], cy[PXT], m1v[PXT], m2v[PXT];
    #pragma unroll
    for (int k = 0; k < PXT; k++) {
        int r = r0 + rsub + k * ROWSUB;
        int p = r * IMG_D + col;
        cx[k]  = __ldg(Cn + p);
        cy[k]  = __ldg(Cn + HW + p);
        m1v[k] = __ldg(M1n + p);
        m2v[k] = __ldg(M2n + p);
    }

    float acc[3][PXT];
    #pragma unroll
    for (int c = 0; c < 3; c++)
        #pragma unroll
        for (int k = 0; k < PXT; k++) acc[c][k] = 0.0f;

    #pragma unroll
    for (int img = 0; img < 2; img++) {
        uint32_t mbar = (img == 0) ? mbar0 : mbar1;
        {
            uint32_t done;
            asm volatile(
                "{\n\t"
                ".reg .pred p;\n\t"
                "mbarrier.try_wait.parity.acquire.cta.shared::cta.b64 p, [%1], 0;\n\t"
                "selp.b32 %0, 1, 0, p;\n\t"
                "}"
                : "=r"(done) : "r"(mbar) : "memory");
            if (!done) {
                asm volatile(
                    "{\n\t"
                    ".reg .pred P1;\n\t"
                    "WL_%=:\n\t"
                    "mbarrier.try_wait.parity.acquire.cta.shared::cta.b64 P1, [%0], 0, 0x989680;\n\t"
                    "@P1 bra.uni WD_%=;\n\t"
                    "bra.uni WL_%=;\n\t"
                    "WD_%=:\n\t"
                    "}"
                    :: "r"(mbar) : "memory");
            }
        }

        float s = (img == 0) ? 1.0f : -1.0f;
        const float* gb = (img == 0) ? b1 : b2;
        const float* spp = sp + img * 3 * PLANE_W;

        #pragma unroll
        for (int k = 0; k < PXT; k++) {
            int r = r0 + rsub + k * ROWSUB;
            float fr = (float)r, fc = (float)col;
            float m = (img == 0) ? m1v[k] : m2v[k];

            float x = fr + s * cx[k];
            float y = fc + s * cy[k];
            x = fminf(fmaxf(x, 0.001f), (float)IMG_D - 1.001f);
            y = fminf(fmaxf(y, 0.001f), (float)IMG_D - 1.001f);

            int ixf = __float2int_rd(x);
            int ixc = __float2int_ru(x);
            int iyf = __float2int_rd(y);
            int iyc = __float2int_ru(y);

            float wxf = 1.0f - (x - (float)ixf);
            float wxc = 1.0f - ((float)ixc - x);
            float wyf = 1.0f - (y - (float)iyf);
            float wyc = 1.0f - ((float)iyc - y);

            float w00 = wxf * wyf;
            float w10 = wxc * wyf;
            float w01 = wxf * wyc;
            float w11 = wxc * wyc;

            int rf = ixf - wl;
            int rc = ixc - wl;
            bool ok = ((unsigned)rf < (unsigned)wc) &
                      ((unsigned)rc < (unsigned)wc);

            float v00[3], v10[3], v01[3], v11[3];
            if (ok) {
                const float* smf = spp + rf * IMG_D;
                const float* smc = spp + rc * IMG_D;
                #pragma unroll
                for (int c = 0; c < 3; c++) {
                    v00[c] = smf[c * PLANE_W + iyf];
                    v01[c] = smf[c * PLANE_W + iyc];
                    v10[c] = smc[c * PLANE_W + iyf];
                    v11[c] = smc[c * PLANE_W + iyc];
                }
            } else {
                #pragma unroll
                for (int c = 0; c < 3; c++) {
                    const float* gf = gb + c * HW + ixf * IMG_D;
                    const float* gc = gb + c * HW + ixc * IMG_D;
                    v00[c] = __ldg(gf + iyf);
                    v01[c] = __ldg(gf + iyc);
                    v10[c] = __ldg(gc + iyf);
                    v11[c] = __ldg(gc + iyc);
                }
            }

            #pragma unroll
            for (int c = 0; c < 3; c++) {
                float sv = w00 * v00[c];
                sv += w10 * v10[c];
                sv += w01 * v01[c];
                sv += w11 * v11[c];
                acc[c][k] += m * sv;
            }
        }
    }

    float* outn = out + (size_t)n * 3 * HW;
    #pragma unroll
    for (int c = 0; c < 3; c++) {
        float* op = outn + c * HW + (r0 + rsub) * IMG_D + col;
        #pragma unroll
        for (int k = 0; k < PXT; k++)
            op[k * ROWSUB * IMG_D] = acc[c][k];
    }
}

extern "C" void kernel_launch(void* const* d_in, const int* in_sizes, int n_in,
                              void* d_out, int out_size)
{
    const float* im1 = (const float*)d_in[0];
    const float* im2 = (const float*)d_in[1];
    const float* C   = (const float*)d_in[2];
    const float* M1  = (const float*)d_in[3];
    const float* M2  = (const float*)d_in[4];
    float* out = (float*)d_out;

    cudaFuncSetAttribute(view_morph12_kernel,
                         cudaFuncAttributeMaxDynamicSharedMemorySize,
                         SMEM_BYTES);

    int blocks = NBATCH * TILES_PER_IMG;  // 1792
    view_morph12_kernel<<<blocks, TPB, SMEM_BYTES>>>(im1, im2, C, M1, M2, out);
}